// round 11
// baseline (speedup 1.0000x reference)
#include <cuda_runtime.h>
#include <math.h>
#include <stdint.h>

#define BB 64
#define TD 128
#define TE 256
#define DX 1024
#define HH 1024
#define N3 3072

// ---------------- persistent state (device globals; no allocations) ----------------
__device__ float g_h[2][BB * HH];       // ping-pong GRU state
__device__ float g_ifeed[BB * HH];
__device__ float g_feed[BB * HH];
__device__ float g_fp[4][BB * HH];      // FEED k-split partials
__device__ float g_gxp[4][BB * N3];     // gx k-split partials
__device__ float g_ghp[4][BB * N3];     // gh k-split partials
__device__ float g_hattp[8][BB * HH];   // HATT partials (y*4+z)
__device__ float g_attv[8][BB * HH];    // attention value partials (unnormalized)
__device__ float g_attm[8][BB];         // attention local max
__device__ float g_atts[8][BB];         // attention local expsum
__device__ float g_gxx[(size_t)TD * BB * N3];  // 96MB: x_t @ Wx[1024:] + bxi

__global__ void init64(const float* __restrict__ h_enc) {
    int i = blockIdx.x * blockDim.x + threadIdx.x;
    if (i < BB * HH) { g_h[0][i] = h_enc[i]; g_ifeed[i] = 0.0f; }
}

__device__ __forceinline__ void ffma2(unsigned long long& a,
                                      unsigned long long x, unsigned long long y) {
    asm("fma.rn.f32x2 %0, %1, %2, %0;" : "+l"(a) : "l"(x), "l"(y));
}
__device__ __forceinline__ unsigned long long fadd2(unsigned long long x,
                                                    unsigned long long y) {
    unsigned long long d;
    asm("add.rn.f32x2 %0, %1, %2;" : "=l"(d) : "l"(x), "l"(y));
    return d;
}
__device__ __forceinline__ float lo2(unsigned long long v) {
    return __uint_as_float((unsigned)(v & 0xffffffffull));
}
__device__ __forceinline__ float hi2(unsigned long long v) {
    return __uint_as_float((unsigned)(v >> 32));
}

// ---------------- FFMA2 GEMM core, NT-parameterized --------------------------------
// Block 256 thr = 2 in-block k-halves (kh) x 128 positions (mg 0..15, ng 0..7).
// C tile 64m x NTn. Thread tile 4m x (NT/8)n, f32x2 k-pair accumulators.
// NT=64 (PRE/GXGH): 12 LDS.64 per 32 FFMA2 -> FFMA2-pipe-bound.
// NT=32 (FEED/HATT): as R9.
// MODE 0 PRE : g_gxx[y] = x[:,y,:] @ Wx[1024:] + bxi     grid (48, TD)
// MODE 1 FEED: g_fp[y]  = ifeed[:, y*256:] @ Wfeed[sl]   grid (32, 4)
// MODE 2 GXGH: y 0/1 gx/gh; z k-quarter                  grid (48, 2, 4)
// MODE 3 HATT: y value/h half; z k-quarter; y==0 A-load fuses the attnc softmax
//              merge (8 partials, per-row coefs)         grid (32, 2, 4)
template <int MODE>
__global__ __launch_bounds__(256, 2)
void gk3(const float* __restrict__ pA, const float* __restrict__ pW,
         const float* __restrict__ pW2, const float* __restrict__ pBias, int hsel)
{
    constexpr int NT   = (MODE == 0 || MODE == 2) ? 64 : 32;
    constexpr int NI   = NT / 8;
    constexpr int KW   = (MODE == 0) ? 1024 : 256;
    constexpr int KH   = KW / 2;
    constexpr int CH   = KH / 32;
    constexpr int NDIM = (MODE == 0 || MODE == 2) ? N3 : HH;

    extern __shared__ char dynsmem[];
    float2* sA2 = reinterpret_cast<float2*>(dynsmem);            // [kh][buf][16*64]
    float2* sW2 = reinterpret_cast<float2*>(dynsmem + 32768);    // [kh][buf][16*NT]
    __shared__ float sc[64][10];                                  // MODE3 merge coefs

    const int tid = threadIdx.x;
    const int kh  = tid >> 7;
    const int p   = tid & 127;
    const int mg  = p & 15;
    const int ng  = p >> 4;
    const int n0  = blockIdx.x * NT;

    int y = 0, z = 0;
    const float* A0 = nullptr; size_t lda = HH;
    const float* W = pW;
    int kA = 0, kWoff = 0;
    float* C; size_t ldc;

    if (MODE == 0) {
        A0 = pA + (size_t)blockIdx.y * DX; lda = (size_t)TD * DX;
        C = g_gxx + (size_t)blockIdx.y * BB * N3; ldc = N3;
    } else if (MODE == 1) {
        z = blockIdx.y; kA = kWoff = z * 256;
        A0 = g_ifeed;
        C = g_fp[z]; ldc = HH;
    } else if (MODE == 2) {
        y = blockIdx.y; z = blockIdx.z;
        kA = kWoff = z * 256;
        if (y == 0) { A0 = g_feed;            C = g_gxp[z]; }
        else        { A0 = g_h[hsel]; W = pW2; C = g_ghp[z]; }
        ldc = N3;
    } else {
        y = blockIdx.y; z = blockIdx.z;
        kA = z * 256; kWoff = y * HH + z * 256;
        if (y) A0 = g_h[hsel];
        C = g_hattp[y * 4 + z]; ldc = HH;
    }

    // MODE3 y==0: per-row (batch) softmax merge coefficients
    if (MODE == 3 && y == 0) {
        if (tid < 64) {
            float mz[8];
            float M = -1e30f;
            #pragma unroll
            for (int q = 0; q < 8; ++q) { mz[q] = g_attm[q][tid]; M = fmaxf(M, mz[q]); }
            float S = 0.f;
            #pragma unroll
            for (int q = 0; q < 8; ++q) {
                float cq = expf(mz[q] - M);
                sc[tid][q] = cq;
                S += g_atts[q][tid] * cq;
            }
            sc[tid][8] = 1.0f / S;
        }
        __syncthreads();
    }

    auto fetchA = [&](int m, int k) -> float4 {
        if (MODE == 3 && y == 0) {
            const float* c = sc[m];
            float4 s = make_float4(0.f, 0.f, 0.f, 0.f);
            #pragma unroll
            for (int q = 0; q < 8; ++q) {
                float4 vq = *reinterpret_cast<const float4*>(&g_attv[q][m * HH + k]);
                float cq = c[q];
                s.x = fmaf(vq.x, cq, s.x);
                s.y = fmaf(vq.y, cq, s.y);
                s.z = fmaf(vq.z, cq, s.z);
                s.w = fmaf(vq.w, cq, s.w);
            }
            float inv = c[8];
            s.x *= inv; s.y *= inv; s.z *= inv; s.w *= inv;
            return s;
        }
        return *reinterpret_cast<const float4*>(A0 + (size_t)m * lda + k);
    };

    float4 ra[4];
    float2 rw[NI];

    auto ldg = [&](int c) {
        const int kc = kA + kh * KH + c * 32;
        #pragma unroll
        for (int i = 0; i < 4; ++i) {
            int idx = i * 128 + p;
            int m = idx >> 3, kq = idx & 7;
            ra[i] = fetchA(m, kc + kq * 4);
        }
        const int kw = kWoff + kh * KH + c * 32;
        #pragma unroll
        for (int i = 0; i < NI; ++i) {
            int idx = i * 128 + p;
            int n = idx % NT, kp2 = idx / NT;
            rw[i].x = W[(size_t)(kw + 2 * kp2)     * NDIM + n0 + n];
            rw[i].y = W[(size_t)(kw + 2 * kp2 + 1) * NDIM + n0 + n];
        }
    };
    auto sts = [&](int buf) {
        float2* sa = sA2 + (kh * 2 + buf) * (16 * 64);
        float2* sw = sW2 + (kh * 2 + buf) * (16 * NT);
        #pragma unroll
        for (int i = 0; i < 4; ++i) {
            int idx = i * 128 + p;
            int m = idx >> 3, kq = idx & 7;
            int kp0 = 2 * kq, kp1 = kp0 + 1;
            sa[kp0 * 64 + (m ^ kp0)] = make_float2(ra[i].x, ra[i].y);
            sa[kp1 * 64 + (m ^ kp1)] = make_float2(ra[i].z, ra[i].w);
        }
        #pragma unroll
        for (int i = 0; i < NI; ++i) {
            int idx = i * 128 + p;
            int n = idx % NT, kp2 = idx / NT;
            sw[kp2 * NT + n] = rw[i];
        }
    };

    unsigned long long acc[4][NI];
    #pragma unroll
    for (int mi = 0; mi < 4; ++mi)
        #pragma unroll
        for (int ni = 0; ni < NI; ++ni) acc[mi][ni] = 0ull;

    ldg(0); sts(0); __syncthreads();

    #pragma unroll 1
    for (int c = 0; c < CH; ++c) {
        if (c + 1 < CH) ldg(c + 1);
        const float2* sa = sA2 + (kh * 2 + (c & 1)) * (16 * 64);
        const float2* sw = sW2 + (kh * 2 + (c & 1)) * (16 * NT);
        #pragma unroll
        for (int kp = 0; kp < 16; ++kp) {
            unsigned long long av[4], wv[NI];
            #pragma unroll
            for (int mi = 0; mi < 4; ++mi)
                av[mi] = *reinterpret_cast<const unsigned long long*>(
                    &sa[kp * 64 + ((mg ^ kp) + 16 * mi)]);
            #pragma unroll
            for (int ni = 0; ni < NI; ++ni)
                wv[ni] = *reinterpret_cast<const unsigned long long*>(
                    &sw[kp * NT + ng + 8 * ni]);
            #pragma unroll
            for (int mi = 0; mi < 4; ++mi)
                #pragma unroll
                for (int ni = 0; ni < NI; ++ni)
                    ffma2(acc[mi][ni], av[mi], wv[ni]);
        }
        if (c + 1 < CH) sts((c + 1) & 1);
        __syncthreads();
    }

    // combine the two in-block k-halves (NI/4 rounds of 16 accs via smem)
    unsigned long long* red = reinterpret_cast<unsigned long long*>(dynsmem);
    #pragma unroll
    for (int h = 0; h < NI / 4; ++h) {
        if (kh == 1) {
            unsigned long long* d = red + (size_t)p * 17;
            #pragma unroll
            for (int mi = 0; mi < 4; ++mi)
                #pragma unroll
                for (int nj = 0; nj < 4; ++nj) d[mi * 4 + nj] = acc[mi][h * 4 + nj];
        }
        __syncthreads();
        if (kh == 0) {
            const unsigned long long* s = red + (size_t)p * 17;
            #pragma unroll
            for (int mi = 0; mi < 4; ++mi)
                #pragma unroll
                for (int nj = 0; nj < 4; ++nj)
                    acc[mi][h * 4 + nj] = fadd2(acc[mi][h * 4 + nj], s[mi * 4 + nj]);
        }
        __syncthreads();
    }

    if (kh == 0) {
        #pragma unroll
        for (int mi = 0; mi < 4; ++mi) {
            const int m = mg + 16 * mi;
            #pragma unroll
            for (int ni = 0; ni < NI; ++ni) {
                const int n = n0 + ng + 8 * ni;
                unsigned long long t2 = acc[mi][ni];
                float v = lo2(t2) + hi2(t2);
                if (MODE == 0) v += pBias[n];
                C[(size_t)m * ldc + n] = v;
            }
        }
    }
}

// ---------------- FEED combine ------------------------------------------------------
__global__ void feedcomb(const float* __restrict__ bfeed) {
    int idx = blockIdx.x * blockDim.x + threadIdx.x;
    int n = idx & 1023;
    g_feed[idx] = tanhf(g_fp[0][idx] + g_fp[1][idx] + g_fp[2][idx] + g_fp[3][idx]
                        + bfeed[n]);
}

// ---------------- GRU gate kernel (no redundancy) -----------------------------------
__global__ __launch_bounds__(256)
void gru(const float* __restrict__ bhr, int t)
{
    const int b = blockIdx.x;
    const int i = blockIdx.y * 256 + threadIdx.x;
    const int i0 = b * N3 + i, i1 = i0 + HH, i2 = i0 + 2 * HH;
    const float* gxx = g_gxx + (size_t)t * BB * N3 + (size_t)b * N3;
    float xz  = g_gxp[0][i0] + g_gxp[1][i0] + g_gxp[2][i0] + g_gxp[3][i0] + gxx[i];
    float xr  = g_gxp[0][i1] + g_gxp[1][i1] + g_gxp[2][i1] + g_gxp[3][i1] + gxx[HH + i];
    float xh  = g_gxp[0][i2] + g_gxp[1][i2] + g_gxp[2][i2] + g_gxp[3][i2] + gxx[2 * HH + i];
    float hz  = g_ghp[0][i0] + g_ghp[1][i0] + g_ghp[2][i0] + g_ghp[3][i0] + bhr[i];
    float hr  = g_ghp[0][i1] + g_ghp[1][i1] + g_ghp[2][i1] + g_ghp[3][i1] + bhr[HH + i];
    float hh2 = g_ghp[0][i2] + g_ghp[1][i2] + g_ghp[2][i2] + g_ghp[3][i2] + bhr[2 * HH + i];
    float hp  = g_h[t & 1][b * HH + i];
    float zz = 1.0f / (1.0f + expf(-(xz + hz)));
    float rr = 1.0f / (1.0f + expf(-(xr + hr)));
    float hc = tanhf(xh + rr * hh2);
    g_h[(t + 1) & 1][b * HH + i] = zz * hp + (1.0f - zz) * hc;
}

// ---------------- partial attention (no GRU): grid (64, 8), 256 thr -----------------
// Forced 1 block/SM via 128KB dynamic smem so the 128KB o_enc slice stays L1-resident
// between the score pass and the value pass.
__global__ __launch_bounds__(256)
void attnp(const float* __restrict__ o_enc, int t)
{
    extern __shared__ char dynsmem[];
    float* sh = reinterpret_cast<float*>(dynsmem);          // [HH]
    float* sp = reinterpret_cast<float*>(dynsmem + HH * 4); // [32]

    const int b = blockIdx.x;
    const int z = blockIdx.y;
    const int tid = threadIdx.x;
    const int w = tid >> 5;
    const int l = tid & 31;

    // stage h_new
    const float* hn = g_h[(t + 1) & 1] + b * HH;
    *reinterpret_cast<float4*>(&sh[tid * 4]) =
        *reinterpret_cast<const float4*>(hn + tid * 4);
    __syncthreads();

    // scores for 32 rows (8 warps x 4 rows)
    const float* ob = o_enc + (size_t)b * TE * HH + (size_t)z * 32 * HH;
    #pragma unroll
    for (int tt = 0; tt < 4; ++tt) {
        int tl = w * 4 + tt;
        const float* orow = ob + tl * HH;
        float s = 0.0f;
        #pragma unroll
        for (int jj = 0; jj < 8; ++jj) {
            int i = (jj << 7) + (l << 2);
            float4 o4 = *reinterpret_cast<const float4*>(orow + i);
            float4 h4 = *reinterpret_cast<const float4*>(sh + i);
            s += o4.x * h4.x + o4.y * h4.y + o4.z * h4.z + o4.w * h4.w;
        }
        #pragma unroll
        for (int off = 16; off > 0; off >>= 1)
            s += __shfl_xor_sync(0xffffffffu, s, off);
        if (l == 0) sp[tl] = s;
    }
    __syncthreads();

    // local softmax stats over 32 (warp 0)
    if (tid < 32) {
        float v = sp[l];
        float M = v;
        #pragma unroll
        for (int off = 16; off > 0; off >>= 1)
            M = fmaxf(M, __shfl_xor_sync(0xffffffffu, M, off));
        float e = expf(v - M);
        float S = e;
        #pragma unroll
        for (int off = 16; off > 0; off >>= 1)
            S += __shfl_xor_sync(0xffffffffu, S, off);
        sp[l] = e;
        if (l == 0) { g_attm[z][b] = M; g_atts[z][b] = S; }
    }
    __syncthreads();

    // unnormalized value partial (256 thr x float4) — o_enc slice L1-hot
    float4 a = make_float4(0.f, 0.f, 0.f, 0.f);
    const int col = tid << 2;
    #pragma unroll 4
    for (int te = 0; te < 32; ++te) {
        float pp = sp[te];
        float4 o4 = *reinterpret_cast<const float4*>(ob + te * HH + col);
        a.x = fmaf(pp, o4.x, a.x);
        a.y = fmaf(pp, o4.y, a.y);
        a.z = fmaf(pp, o4.z, a.z);
        a.w = fmaf(pp, o4.w, a.w);
    }
    *reinterpret_cast<float4*>(&g_attv[z][b * HH + col]) = a;
}

// ---------------- HATT combine ------------------------------------------------------
__global__ void combine_hatt(float* __restrict__ out, const float* __restrict__ batt) {
    int idx = blockIdx.x * blockDim.x + threadIdx.x;
    int m = idx >> 10, n = idx & 1023;
    float v = g_hattp[0][idx] + g_hattp[1][idx] + g_hattp[2][idx] + g_hattp[3][idx]
            + g_hattp[4][idx] + g_hattp[5][idx] + g_hattp[6][idx] + g_hattp[7][idx]
            + batt[n];
    v = tanhf(v);
    out[(size_t)m * TD * HH + n] = v;
    g_ifeed[idx] = v;
}

// ---------------- launcher ----------------------------------------------------------
extern "C" void kernel_launch(void* const* d_in, const int* in_sizes, int n_in,
                              void* d_out, int out_size)
{
    const float* x      = (const float*)d_in[0];
    const float* o_enc  = (const float*)d_in[1];
    const float* h_enc  = (const float*)d_in[2];
    const float* Wfeed  = (const float*)d_in[3];
    const float* bfeed  = (const float*)d_in[4];
    const float* Wx     = (const float*)d_in[5];
    const float* Wh     = (const float*)d_in[6];
    const float* bxi    = (const float*)d_in[7];
    const float* bhr    = (const float*)d_in[8];
    const float* Watt   = (const float*)d_in[9];
    const float* batt   = (const float*)d_in[10];
    float* out = (float*)d_out;

    const int SM64 = 65536;   // NT=64 modes: 32KB A + 32KB W
    const int SM32 = 49152;   // NT=32 modes: 32KB A + 16KB W
    const int SMAT = 131072;  // attnp: force 1 block/SM
    cudaFuncSetAttribute(gk3<0>, cudaFuncAttributeMaxDynamicSharedMemorySize, SM64);
    cudaFuncSetAttribute(gk3<1>, cudaFuncAttributeMaxDynamicSharedMemorySize, SM32);
    cudaFuncSetAttribute(gk3<2>, cudaFuncAttributeMaxDynamicSharedMemorySize, SM64);
    cudaFuncSetAttribute(gk3<3>, cudaFuncAttributeMaxDynamicSharedMemorySize, SM32);
    cudaFuncSetAttribute(attnp, cudaFuncAttributeMaxDynamicSharedMemorySize, SMAT);

    init64<<<64, 1024>>>(h_enc);

    // precompute g_gxx[t] = x_t @ Wx[1024:] + bxi (recurrence-independent)
    gk3<0><<<dim3(48, TD), 256, SM64>>>(x, Wx + (size_t)HH * N3, nullptr, bxi, 0);

    for (int t = 0; t < TD; ++t) {
        gk3<1><<<dim3(32, 4), 256, SM32>>>(nullptr, Wfeed, nullptr, nullptr, 0);
        feedcomb<<<128, 512>>>(bfeed);
        gk3<2><<<dim3(48, 2, 4), 256, SM64>>>(nullptr, Wx, Wh, nullptr, t & 1);
        gru<<<dim3(BB, 4), 256>>>(bhr, t);
        attnp<<<dim3(BB, 8), 256, SMAT>>>(o_enc, t);
        gk3<3><<<dim3(32, 2, 4), 256, SM32>>>(nullptr, Watt, nullptr, nullptr, (t + 1) & 1);
        combine_hatt<<<128, 512>>>(out + (size_t)t * HH, batt);
    }
}

// round 14
// speedup vs baseline: 1.1275x; 1.1275x over previous
#include <cuda_runtime.h>
#include <math.h>
#include <stdint.h>

#define BB 64
#define TD 128
#define TE 256
#define DX 1024
#define HH 1024
#define N3 3072

// ---------------- persistent state (device globals; no allocations) ----------------
__device__ float g_h[2][BB * HH];       // ping-pong GRU state
__device__ float g_ifeed[BB * HH];
__device__ float g_feed[BB * HH];
__device__ float g_value[BB * HH];
__device__ float g_fp[4][BB * HH];      // FEED k-split partials
__device__ float g_gxp[4][BB * N3];     // gx k-split partials
__device__ float g_ghp[4][BB * N3];     // gh k-split partials
__device__ float g_hattp[8][BB * HH];   // HATT partials (0..3 value-half, 4..7 h-half)
__device__ float g_attv[4][BB * HH];    // attention value partials (unnormalized)
__device__ float g_attm[4][BB];         // attention local max
__device__ float g_atts[4][BB];         // attention local expsum
__device__ float g_gxx[(size_t)TD * BB * N3];  // 96MB: x_t @ Wx[1024:] + bxi

__global__ void init64(const float* __restrict__ h_enc) {
    int i = blockIdx.x * blockDim.x + threadIdx.x;
    if (i < BB * HH) { g_h[0][i] = h_enc[i]; g_ifeed[i] = 0.0f; }
}

__device__ __forceinline__ void ffma2(unsigned long long& a,
                                      unsigned long long x, unsigned long long y) {
    asm("fma.rn.f32x2 %0, %1, %2, %0;" : "+l"(a) : "l"(x), "l"(y));
}
__device__ __forceinline__ unsigned long long fadd2(unsigned long long x,
                                                    unsigned long long y) {
    unsigned long long d;
    asm("add.rn.f32x2 %0, %1, %2;" : "=l"(d) : "l"(x), "l"(y));
    return d;
}
__device__ __forceinline__ float lo2(unsigned long long v) {
    return __uint_as_float((unsigned)(v & 0xffffffffull));
}
__device__ __forceinline__ float hi2(unsigned long long v) {
    return __uint_as_float((unsigned)(v >> 32));
}

// attnc body (256 threads): merge 4 partial softmaxes for batch row b -> g_value
__device__ __forceinline__ void attnc_body(int b) {
    const int tid = threadIdx.x;
    float m0 = g_attm[0][b], m1 = g_attm[1][b], m2 = g_attm[2][b], m3 = g_attm[3][b];
    float M = fmaxf(fmaxf(m0, m1), fmaxf(m2, m3));
    float c0 = expf(m0 - M), c1 = expf(m1 - M), c2 = expf(m2 - M), c3 = expf(m3 - M);
    float inv = 1.0f / (g_atts[0][b] * c0 + g_atts[1][b] * c1 +
                        g_atts[2][b] * c2 + g_atts[3][b] * c3);
    #pragma unroll
    for (int cc = 0; cc < 2; ++cc) {
        int col = (tid + cc * 256) * 2;
        float2 v0 = *reinterpret_cast<const float2*>(&g_attv[0][b * HH + col]);
        float2 v1 = *reinterpret_cast<const float2*>(&g_attv[1][b * HH + col]);
        float2 v2 = *reinterpret_cast<const float2*>(&g_attv[2][b * HH + col]);
        float2 v3 = *reinterpret_cast<const float2*>(&g_attv[3][b * HH + col]);
        float2 r;
        r.x = (v0.x * c0 + v1.x * c1 + v2.x * c2 + v3.x * c3) * inv;
        r.y = (v0.y * c0 + v1.y * c1 + v2.y * c2 + v3.y * c3) * inv;
        *reinterpret_cast<float2*>(&g_value[b * HH + col]) = r;
    }
}

// ---------------- FFMA2 GEMM core (champion inner loop, VERBATIM) -------------------
// Block 256 thr = 2 in-block k-halves (kh) x 128 positions (mg 0..15, ng 0..7).
// C tile 64m x 32n. Thread tile 4m x 4n strided; 16 f32x2 k-pair accumulators.
// MODE 0 PRE    : g_gxx[y] = x[:,y,:] @ Wx[1024:] + bxi        grid (96, TD)
// MODE 1 FEED+GH: z<4 gh (x<96); z>=4 FEED (x<32)              grid (96, 1, 8)
// MODE 2 GX     : g_gxp[z] = feed @ Wx[:1024] k-quarter        grid (96, 1, 4)
// MODE 3 ATTNC+HATTH: z<4 hatt_h (x<32); z>=4 attnc (x<16)     grid (32, 1, 8)
// MODE 4 HATTV  : g_hattp[z] = value @ Watt[:1024] k-quarter   grid (32, 1, 4)
template <int MODE>
__global__ __launch_bounds__(256, 2)
void gk2(const float* __restrict__ pA, const float* __restrict__ pW,
         const float* __restrict__ pW2, const float* __restrict__ pBias, int hsel)
{
    constexpr int KW   = (MODE == 0) ? 1024 : 256;
    constexpr int KH   = KW / 2;
    constexpr int CH   = KH / 32;

    __shared__ __align__(16) float2 sA2[2][2][16 * 64];   // 32KB
    __shared__ __align__(16) float2 sW2[2][2][16 * 32];   // 16KB

    const int tid = threadIdx.x;
    const int kh  = tid >> 7;
    const int p   = tid & 127;
    const int mg  = p & 15;
    const int ng  = p >> 4;
    const int n0  = blockIdx.x * 32;

    const float* A0; size_t lda = HH;
    const float* W = pW;
    int kA = 0, kW2 = 0;
    int NDIM;                      // W row stride (runtime; constant-folds per mode)
    float* C; size_t ldc;

    if (MODE == 0) {
        A0 = pA + (size_t)blockIdx.y * DX; lda = (size_t)TD * DX;
        C = g_gxx + (size_t)blockIdx.y * BB * N3; ldc = N3; NDIM = N3;
    } else if (MODE == 1) {
        if (blockIdx.z < 4) {            // gh: h[t] @ Wh k-quarter
            const int z = blockIdx.z;
            A0 = g_h[hsel]; W = pW2; kA = kW2 = z * 256;
            C = g_ghp[z]; ldc = N3; NDIM = N3;
        } else {                         // FEED: ifeed @ Wfeed k-quarter
            if (blockIdx.x >= 32) return;
            const int z = blockIdx.z - 4;
            A0 = g_ifeed; kA = kW2 = z * 256;
            C = g_fp[z]; ldc = HH; NDIM = HH;
        }
    } else if (MODE == 2) {
        const int z = blockIdx.z;
        A0 = g_feed; kA = kW2 = z * 256;
        C = g_gxp[z]; ldc = N3; NDIM = N3;
    } else if (MODE == 3) {
        if (blockIdx.z >= 4) {           // attnc
            if (blockIdx.x >= 16) return;
            attnc_body((blockIdx.z - 4) * 16 + blockIdx.x);
            return;
        }
        const int z = blockIdx.z;        // hatt_h: h[t+1] @ Watt[1024:] k-quarter
        A0 = g_h[hsel]; kA = z * 256; kW2 = HH + z * 256;
        C = g_hattp[4 + z]; ldc = HH; NDIM = HH;
    } else {                             // MODE 4: hatt_v
        const int z = blockIdx.z;
        A0 = g_value; kA = kW2 = z * 256;
        C = g_hattp[z]; ldc = HH; NDIM = HH;
    }

    const int kbA = kA + kh * KH;
    const int kbW = kW2 + kh * KH;

    float4 ra[4];
    float2 rw[4];

    auto ldg = [&](int c) {
        const int kc = kbA + c * 32;
        #pragma unroll
        for (int i = 0; i < 4; ++i) {
            int idx = i * 128 + p;
            int m = idx >> 3, kq = idx & 7;
            ra[i] = *reinterpret_cast<const float4*>(A0 + (size_t)m * lda + kc + kq * 4);
        }
        const int kw = kbW + c * 32;
        #pragma unroll
        for (int i = 0; i < 4; ++i) {
            int idx = i * 128 + p;
            int n = idx & 31, kp = idx >> 5;
            rw[i].x = W[(size_t)(kw + 2 * kp)     * NDIM + n0 + n];
            rw[i].y = W[(size_t)(kw + 2 * kp + 1) * NDIM + n0 + n];
        }
    };
    auto sts = [&](int b) {
        float2* sa = sA2[kh][b];
        float2* sw = sW2[kh][b];
        #pragma unroll
        for (int i = 0; i < 4; ++i) {
            int idx = i * 128 + p;
            int m = idx >> 3, kq = idx & 7;
            int kp0 = 2 * kq, kp1 = 2 * kq + 1;
            sa[kp0 * 64 + (m ^ kp0)] = make_float2(ra[i].x, ra[i].y);
            sa[kp1 * 64 + (m ^ kp1)] = make_float2(ra[i].z, ra[i].w);
        }
        #pragma unroll
        for (int i = 0; i < 4; ++i) {
            int idx = i * 128 + p;
            int n = idx & 31, kp = idx >> 5;
            sw[kp * 32 + n] = rw[i];
        }
    };

    unsigned long long acc[4][4];
    #pragma unroll
    for (int mi = 0; mi < 4; ++mi)
        #pragma unroll
        for (int ni = 0; ni < 4; ++ni) acc[mi][ni] = 0ull;

    ldg(0); sts(0); __syncthreads();

    #pragma unroll 1
    for (int c = 0; c < CH; ++c) {
        if (c + 1 < CH) ldg(c + 1);
        const float2* sa = sA2[kh][c & 1];
        const float2* sw = sW2[kh][c & 1];
        #pragma unroll
        for (int kp = 0; kp < 16; ++kp) {
            const int mgx = mg ^ kp;
            unsigned long long av[4], wv[4];
            #pragma unroll
            for (int mi = 0; mi < 4; ++mi)
                av[mi] = *reinterpret_cast<const unsigned long long*>(
                    &sa[kp * 64 + mgx + 16 * mi]);
            #pragma unroll
            for (int ni = 0; ni < 4; ++ni)
                wv[ni] = *reinterpret_cast<const unsigned long long*>(
                    &sw[kp * 32 + ng + 8 * ni]);
            #pragma unroll
            for (int mi = 0; mi < 4; ++mi)
                #pragma unroll
                for (int ni = 0; ni < 4; ++ni)
                    ffma2(acc[mi][ni], av[mi], wv[ni]);
        }
        if (c + 1 < CH) sts((c + 1) & 1);
        __syncthreads();
    }

    // combine 2 in-block k-halves: one smem roundtrip (staggered rows)
    unsigned long long* red = reinterpret_cast<unsigned long long*>(&sA2[0][0][0]);
    if (kh == 1) {
        unsigned long long* d = red + (size_t)p * 17;
        #pragma unroll
        for (int mi = 0; mi < 4; ++mi)
            #pragma unroll
            for (int ni = 0; ni < 4; ++ni) d[mi * 4 + ni] = acc[mi][ni];
    }
    __syncthreads();
    if (kh == 0) {
        const unsigned long long* s = red + (size_t)p * 17;
        #pragma unroll
        for (int mi = 0; mi < 4; ++mi) {
            #pragma unroll
            for (int ni = 0; ni < 4; ++ni) {
                unsigned long long tv = fadd2(acc[mi][ni], s[mi * 4 + ni]);
                float v = lo2(tv) + hi2(tv);
                const int m = mg + 16 * mi;
                const int n = n0 + ng + 8 * ni;
                if (MODE == 0) v += pBias[n];
                C[(size_t)m * ldc + n] = v;
            }
        }
    }
}

// ---------------- FEED combine ------------------------------------------------------
__global__ void feedcomb(const float* __restrict__ bfeed) {
    int idx = blockIdx.x * blockDim.x + threadIdx.x;
    int n = idx & 1023;
    g_feed[idx] = tanhf(g_fp[0][idx] + g_fp[1][idx] + g_fp[2][idx] + g_fp[3][idx]
                        + bfeed[n]);
}

// ---------------- fused GRU + partial attention (champion, verbatim) ----------------
__global__ __launch_bounds__(512)
void attnp(const float* __restrict__ o_enc, const float* __restrict__ bhr, int t)
{
    __shared__ __align__(16) float sh[HH];
    __shared__ float sp[64];
    __shared__ float red[8];

    const int b = blockIdx.x;
    const int z = blockIdx.y;
    const int tid = threadIdx.x;
    const int w = tid >> 5;
    const int l = tid & 31;
    const int hsel = t & 1;

    const float* gxx = g_gxx + (size_t)t * BB * N3 + (size_t)b * N3;
    const float* hcur = g_h[hsel];
    float* hnxt = g_h[hsel ^ 1];

    #pragma unroll
    for (int r = 0; r < 2; ++r) {
        int i = (r << 9) + tid;
        int i0 = b * N3 + i, i1 = i0 + HH, i2 = i0 + 2 * HH;
        float xz  = g_gxp[0][i0] + g_gxp[1][i0] + g_gxp[2][i0] + g_gxp[3][i0] + gxx[i];
        float xr  = g_gxp[0][i1] + g_gxp[1][i1] + g_gxp[2][i1] + g_gxp[3][i1] + gxx[HH + i];
        float xh  = g_gxp[0][i2] + g_gxp[1][i2] + g_gxp[2][i2] + g_gxp[3][i2] + gxx[2 * HH + i];
        float hz  = g_ghp[0][i0] + g_ghp[1][i0] + g_ghp[2][i0] + g_ghp[3][i0] + bhr[i];
        float hr  = g_ghp[0][i1] + g_ghp[1][i1] + g_ghp[2][i1] + g_ghp[3][i1] + bhr[HH + i];
        float hh2 = g_ghp[0][i2] + g_ghp[1][i2] + g_ghp[2][i2] + g_ghp[3][i2] + bhr[2 * HH + i];
        float hp  = hcur[b * HH + i];
        float zz = 1.0f / (1.0f + expf(-(xz + hz)));
        float rr = 1.0f / (1.0f + expf(-(xr + hr)));
        float hc = tanhf(xh + rr * hh2);
        float hn = zz * hp + (1.0f - zz) * hc;
        sh[i] = hn;
        if (z == 0) hnxt[b * HH + i] = hn;
    }
    __syncthreads();

    const float* ob = o_enc + (size_t)b * TE * HH;
    #pragma unroll
    for (int tt = 0; tt < 4; ++tt) {
        int tl = (w << 2) + tt;
        const float* orow = ob + (z * 64 + tl) * HH;
        float s = 0.0f;
        #pragma unroll
        for (int jj = 0; jj < 8; ++jj) {
            int i = (jj << 7) + (l << 2);
            float4 o4 = *reinterpret_cast<const float4*>(orow + i);
            float4 h4 = *reinterpret_cast<const float4*>(sh + i);
            s += o4.x * h4.x + o4.y * h4.y + o4.z * h4.z + o4.w * h4.w;
        }
        #pragma unroll
        for (int off = 16; off > 0; off >>= 1)
            s += __shfl_xor_sync(0xffffffffu, s, off);
        if (l == 0) sp[tl] = s;
    }
    __syncthreads();

    float v = 0.0f;
    if (tid < 64) {
        v = sp[tid];
        float M = v;
        #pragma unroll
        for (int off = 16; off > 0; off >>= 1)
            M = fmaxf(M, __shfl_xor_sync(0xffffffffu, M, off));
        if (l == 0) red[w] = M;
    }
    __syncthreads();
    const float M = fmaxf(red[0], red[1]);
    if (tid < 64) {
        float e = expf(v - M);
        float S = e;
        #pragma unroll
        for (int off = 16; off > 0; off >>= 1)
            S += __shfl_xor_sync(0xffffffffu, S, off);
        if (l == 0) red[2 + w] = S;
        sp[tid] = e;
    }
    __syncthreads();
    if (tid == 0) { g_attm[z][b] = M; g_atts[z][b] = red[2] + red[3]; }

    float2 a = make_float2(0.f, 0.f);
    const int col = tid << 1;
    const float* obz = ob + z * 64 * HH;
    #pragma unroll 4
    for (int te = 0; te < 64; ++te) {
        float pp = sp[te];
        float2 o2 = *reinterpret_cast<const float2*>(obz + te * HH + col);
        a.x = fmaf(pp, o2.x, a.x);
        a.y = fmaf(pp, o2.y, a.y);
    }
    *reinterpret_cast<float2*>(&g_attv[z][b * HH + col]) = a;
}

// ---------------- HATT combine ------------------------------------------------------
__global__ void combine_hatt(float* __restrict__ out, const float* __restrict__ batt) {
    int idx = blockIdx.x * blockDim.x + threadIdx.x;
    int m = idx >> 10, n = idx & 1023;
    float v = g_hattp[0][idx] + g_hattp[1][idx] + g_hattp[2][idx] + g_hattp[3][idx]
            + g_hattp[4][idx] + g_hattp[5][idx] + g_hattp[6][idx] + g_hattp[7][idx]
            + batt[n];
    v = tanhf(v);
    out[(size_t)m * TD * HH + n] = v;
    g_ifeed[idx] = v;
}

// ---------------- launcher ----------------------------------------------------------
extern "C" void kernel_launch(void* const* d_in, const int* in_sizes, int n_in,
                              void* d_out, int out_size)
{
    const float* x      = (const float*)d_in[0];
    const float* o_enc  = (const float*)d_in[1];
    const float* h_enc  = (const float*)d_in[2];
    const float* Wfeed  = (const float*)d_in[3];
    const float* bfeed  = (const float*)d_in[4];
    const float* Wx     = (const float*)d_in[5];
    const float* Wh     = (const float*)d_in[6];
    const float* bxi    = (const float*)d_in[7];
    const float* bhr    = (const float*)d_in[8];
    const float* Watt   = (const float*)d_in[9];
    const float* batt   = (const float*)d_in[10];
    float* out = (float*)d_out;

    init64<<<64, 1024>>>(h_enc);

    // precompute g_gxx[t] = x_t @ Wx[1024:] + bxi (recurrence-independent)
    gk2<0><<<dim3(96, TD), 256>>>(x, Wx + (size_t)HH * N3, nullptr, bxi, 0);

    for (int t = 0; t < TD; ++t) {
        // FEED (z>=4, x<32) together with gh = h[t] @ Wh (z<4, x<96)
        gk2<1><<<dim3(96, 1, 8), 256>>>(nullptr, Wfeed, Wh, nullptr, t & 1);
        feedcomb<<<128, 512>>>(bfeed);
        // gx = feed @ Wx[:1024] (k-quarters)
        gk2<2><<<dim3(96, 1, 4), 256>>>(nullptr, Wx, nullptr, nullptr, 0);
        // GRU + partial attention (writes h[t+1], attv/attm/atts)
        attnp<<<dim3(BB, 4), 512>>>(o_enc, bhr, t);
        // attnc (z>=4, x<16) together with hatt_h = h[t+1] @ Watt[1024:] (z<4)
        gk2<3><<<dim3(32, 1, 8), 256>>>(nullptr, Watt, nullptr, nullptr, (t + 1) & 1);
        // hatt_v = value @ Watt[:1024]
        gk2<4><<<dim3(32, 1, 4), 256>>>(nullptr, Watt, nullptr, nullptr, 0);
        combine_hatt<<<128, 512>>>(out + (size_t)t * HH, batt);
    }
}

// round 15
// speedup vs baseline: 1.1788x; 1.0455x over previous
#include <cuda_runtime.h>
#include <math.h>
#include <stdint.h>

#define BB 64
#define TD 128
#define TE 256
#define DX 1024
#define HH 1024
#define N3 3072

// ---------------- persistent state (device globals; no allocations) ----------------
__device__ float g_h[2][BB * HH];       // ping-pong GRU state
__device__ float g_ifeed[BB * HH];
__device__ float g_feed[BB * HH];
__device__ float g_value[BB * HH];
__device__ float g_fp[4][BB * HH];      // FEED k-split partials
__device__ float g_gxp[4][BB * N3];     // gx k-split partials
__device__ float g_ghp[4][BB * N3];     // gh k-split partials
__device__ float g_hattp[8][BB * HH];   // HATT partials
__device__ float g_attv[4][BB * HH];    // attention value partials (unnormalized)
__device__ float g_attm[4][BB];         // attention local max
__device__ float g_atts[4][BB];         // attention local expsum
__device__ float g_gxx[(size_t)TD * BB * N3];  // 96MB: x_t @ Wx[1024:] + bxi

__global__ void init64(const float* __restrict__ h_enc) {
    int i = blockIdx.x * blockDim.x + threadIdx.x;
    if (i < BB * HH) { g_h[0][i] = h_enc[i]; g_ifeed[i] = 0.0f; }
}

__device__ __forceinline__ void ffma2(unsigned long long& a,
                                      unsigned long long x, unsigned long long y) {
    asm("fma.rn.f32x2 %0, %1, %2, %0;" : "+l"(a) : "l"(x), "l"(y));
}
__device__ __forceinline__ unsigned long long fadd2(unsigned long long x,
                                                    unsigned long long y) {
    unsigned long long d;
    asm("add.rn.f32x2 %0, %1, %2;" : "=l"(d) : "l"(x), "l"(y));
    return d;
}
__device__ __forceinline__ float lo2(unsigned long long v) {
    return __uint_as_float((unsigned)(v & 0xffffffffull));
}
__device__ __forceinline__ float hi2(unsigned long long v) {
    return __uint_as_float((unsigned)(v >> 32));
}

// ---------------- FFMA2 GEMM core (champion, VERBATIM) ------------------------------
// Block 256 thr = 2 in-block k-halves (kh) x 128 positions. C tile 64m x 32n.
// Thread tile 4m x 4n strided; 16 f32x2 k-pair accumulators.
// MODE 0 PRE : g_gxx[y] = x[:,y,:] @ Wx[1024:] + bxi     grid (96, TD)
// MODE 1 FEED: g_fp[y]  = ifeed[:, y*256:] @ Wfeed[sl]   grid (32, 4)
// MODE 2 GXGH: y 0/1 gx/gh; z k-quarter                  grid (96, 2, 4)
// MODE 3 HATT: y value/h half; z k-quarter               grid (32, 2, 4)
template <int MODE>
__global__ __launch_bounds__(256, 2)
void gk2(const float* __restrict__ pA, const float* __restrict__ pW,
         const float* __restrict__ pW2, const float* __restrict__ pBias, int hsel)
{
    constexpr int KW   = (MODE == 0) ? 1024 : 256;
    constexpr int KH   = KW / 2;
    constexpr int CH   = KH / 32;
    constexpr int NDIM = (MODE == 0 || MODE == 2) ? N3 : HH;

    __shared__ __align__(16) float2 sA2[2][2][16 * 64];   // 32KB
    __shared__ __align__(16) float2 sW2[2][2][16 * 32];   // 16KB

    const int tid = threadIdx.x;
    const int kh  = tid >> 7;
    const int p   = tid & 127;
    const int mg  = p & 15;
    const int ng  = p >> 4;
    const int n0  = blockIdx.x * 32;

    const float* A; size_t lda = HH;
    const float* W = pW;
    int kA = 0, kW2 = 0;
    float* C; size_t ldc;

    if (MODE == 0) {
        A = pA + (size_t)blockIdx.y * DX; lda = (size_t)TD * DX;
        C = g_gxx + (size_t)blockIdx.y * BB * N3; ldc = N3;
    } else if (MODE == 1) {
        const int z = blockIdx.y;
        A = g_ifeed; kA = kW2 = z * 256;
        C = g_fp[z]; ldc = HH;
    } else if (MODE == 2) {
        const int z = blockIdx.z;
        kA = kW2 = z * 256;
        if (blockIdx.y == 0) { A = g_feed;     W = pW;  C = g_gxp[z]; }
        else                 { A = g_h[hsel];  W = pW2; C = g_ghp[z]; }
        ldc = N3;
    } else {
        const int y = blockIdx.y, z = blockIdx.z;
        A = y ? g_h[hsel] : g_value;
        kA = z * 256; kW2 = y * HH + z * 256;
        C = g_hattp[y * 4 + z]; ldc = HH;
    }

    const int kbA = kA + kh * KH;
    const int kbW = kW2 + kh * KH;

    float4 ra[4];
    float2 rw[4];

    auto ldg = [&](int c) {
        const int kc = kbA + c * 32;
        #pragma unroll
        for (int i = 0; i < 4; ++i) {
            int idx = i * 128 + p;
            int m = idx >> 3, kq = idx & 7;
            ra[i] = *reinterpret_cast<const float4*>(A + (size_t)m * lda + kc + kq * 4);
        }
        const int kw = kbW + c * 32;
        #pragma unroll
        for (int i = 0; i < 4; ++i) {
            int idx = i * 128 + p;
            int n = idx & 31, kp = idx >> 5;
            rw[i].x = W[(size_t)(kw + 2 * kp)     * NDIM + n0 + n];
            rw[i].y = W[(size_t)(kw + 2 * kp + 1) * NDIM + n0 + n];
        }
    };
    auto sts = [&](int b) {
        float2* sa = sA2[kh][b];
        float2* sw = sW2[kh][b];
        #pragma unroll
        for (int i = 0; i < 4; ++i) {
            int idx = i * 128 + p;
            int m = idx >> 3, kq = idx & 7;
            int kp0 = 2 * kq, kp1 = 2 * kq + 1;
            sa[kp0 * 64 + (m ^ kp0)] = make_float2(ra[i].x, ra[i].y);
            sa[kp1 * 64 + (m ^ kp1)] = make_float2(ra[i].z, ra[i].w);
        }
        #pragma unroll
        for (int i = 0; i < 4; ++i) {
            int idx = i * 128 + p;
            int n = idx & 31, kp = idx >> 5;
            sw[kp * 32 + n] = rw[i];
        }
    };

    unsigned long long acc[4][4];
    #pragma unroll
    for (int mi = 0; mi < 4; ++mi)
        #pragma unroll
        for (int ni = 0; ni < 4; ++ni) acc[mi][ni] = 0ull;

    ldg(0); sts(0); __syncthreads();

    #pragma unroll 1
    for (int c = 0; c < CH; ++c) {
        if (c + 1 < CH) ldg(c + 1);
        const float2* sa = sA2[kh][c & 1];
        const float2* sw = sW2[kh][c & 1];
        #pragma unroll
        for (int kp = 0; kp < 16; ++kp) {
            const int mgx = mg ^ kp;
            unsigned long long av[4], wv[4];
            #pragma unroll
            for (int mi = 0; mi < 4; ++mi)
                av[mi] = *reinterpret_cast<const unsigned long long*>(
                    &sa[kp * 64 + mgx + 16 * mi]);
            #pragma unroll
            for (int ni = 0; ni < 4; ++ni)
                wv[ni] = *reinterpret_cast<const unsigned long long*>(
                    &sw[kp * 32 + ng + 8 * ni]);
            #pragma unroll
            for (int mi = 0; mi < 4; ++mi)
                #pragma unroll
                for (int ni = 0; ni < 4; ++ni)
                    ffma2(acc[mi][ni], av[mi], wv[ni]);
        }
        if (c + 1 < CH) sts((c + 1) & 1);
        __syncthreads();
    }

    unsigned long long* red = reinterpret_cast<unsigned long long*>(&sA2[0][0][0]);
    if (kh == 1) {
        unsigned long long* d = red + (size_t)p * 17;
        #pragma unroll
        for (int mi = 0; mi < 4; ++mi)
            #pragma unroll
            for (int ni = 0; ni < 4; ++ni) d[mi * 4 + ni] = acc[mi][ni];
    }
    __syncthreads();
    if (kh == 0) {
        const unsigned long long* s = red + (size_t)p * 17;
        #pragma unroll
        for (int mi = 0; mi < 4; ++mi) {
            #pragma unroll
            for (int ni = 0; ni < 4; ++ni) {
                unsigned long long tv = fadd2(acc[mi][ni], s[mi * 4 + ni]);
                float v = lo2(tv) + hi2(tv);
                const int m = mg + 16 * mi;
                const int n = n0 + ng + 8 * ni;
                if (MODE == 0) v += pBias[n];
                C[(size_t)m * ldc + n] = v;
            }
        }
    }
}

// ---------------- FEED combine ------------------------------------------------------
__global__ void feedcomb(const float* __restrict__ bfeed) {
    int idx = blockIdx.x * blockDim.x + threadIdx.x;
    int n = idx & 1023;
    g_feed[idx] = tanhf(g_fp[0][idx] + g_fp[1][idx] + g_fp[2][idx] + g_fp[3][idx]
                        + bfeed[n]);
}

// ---------------- fused GRU + FLASH single-pass partial attention -------------------
// grid (64 b, 4 z), 512 thr. GRU as champion. Then each warp owns 4 te rows:
// loads the row ONCE (d[8] float4 regs), dot -> score, online-softmax accumulate
// (running M,S + 32-float value acc/lane). 16-warp merge via smem + exp rescale.
// Output semantics identical to champion: g_attv (unnormalized at block max),
// g_attm = block max, g_atts = block expsum.
#define ATTN_SMEM ((1024 + 16 * 1032 + 48) * 4)
__global__ __launch_bounds__(512)
void attnp(const float* __restrict__ o_enc, const float* __restrict__ bhr, int t)
{
    extern __shared__ float dynf[];
    float* sh   = dynf;                       // [1024] h_new
    float* sacc = dynf + 1024;                // [16][1032] per-warp value accs
    float* sM   = dynf + 1024 + 16 * 1032;    // [16] warp max -> coef
    float* sS   = sM + 16;                    // [16] warp expsum
    float* sX   = sS + 16;                    // [2]  block M, S

    const int b = blockIdx.x;
    const int z = blockIdx.y;
    const int tid = threadIdx.x;
    const int w = tid >> 5;
    const int l = tid & 31;
    const int hsel = t & 1;

    const float* gxx = g_gxx + (size_t)t * BB * N3 + (size_t)b * N3;
    const float* hcur = g_h[hsel];
    float* hnxt = g_h[hsel ^ 1];

    // phase 1: GRU (reset_after=True), champion-verbatim
    #pragma unroll
    for (int r = 0; r < 2; ++r) {
        int i = (r << 9) + tid;
        int i0 = b * N3 + i, i1 = i0 + HH, i2 = i0 + 2 * HH;
        float xz  = g_gxp[0][i0] + g_gxp[1][i0] + g_gxp[2][i0] + g_gxp[3][i0] + gxx[i];
        float xr  = g_gxp[0][i1] + g_gxp[1][i1] + g_gxp[2][i1] + g_gxp[3][i1] + gxx[HH + i];
        float xh  = g_gxp[0][i2] + g_gxp[1][i2] + g_gxp[2][i2] + g_gxp[3][i2] + gxx[2 * HH + i];
        float hz  = g_ghp[0][i0] + g_ghp[1][i0] + g_ghp[2][i0] + g_ghp[3][i0] + bhr[i];
        float hr  = g_ghp[0][i1] + g_ghp[1][i1] + g_ghp[2][i1] + g_ghp[3][i1] + bhr[HH + i];
        float hh2 = g_ghp[0][i2] + g_ghp[1][i2] + g_ghp[2][i2] + g_ghp[3][i2] + bhr[2 * HH + i];
        float hp  = hcur[b * HH + i];
        float zz = 1.0f / (1.0f + expf(-(xz + hz)));
        float rr = 1.0f / (1.0f + expf(-(xr + hr)));
        float hc = tanhf(xh + rr * hh2);
        float hn = zz * hp + (1.0f - zz) * hc;
        sh[i] = hn;
        if (z == 0) hnxt[b * HH + i] = hn;
    }
    __syncthreads();

    // phase 2: flash pass — warp w handles rows 4w..4w+3 of this z's 64-row slice
    const float* obz = o_enc + (size_t)b * TE * HH + (size_t)z * 64 * HH;
    float M = -1e30f, S = 0.0f;
    float4 acc[8];
    #pragma unroll
    for (int j = 0; j < 8; ++j) acc[j] = make_float4(0.f, 0.f, 0.f, 0.f);

    #pragma unroll 1
    for (int r = 0; r < 4; ++r) {
        const float* row = obz + (w * 4 + r) * HH;
        float4 d[8];
        float dot = 0.0f;
        #pragma unroll
        for (int j = 0; j < 8; ++j) {
            d[j] = *reinterpret_cast<const float4*>(row + j * 128 + l * 4);
            float4 h4 = *reinterpret_cast<const float4*>(sh + j * 128 + l * 4);
            dot += d[j].x * h4.x + d[j].y * h4.y + d[j].z * h4.z + d[j].w * h4.w;
        }
        #pragma unroll
        for (int off = 16; off > 0; off >>= 1)
            dot += __shfl_xor_sync(0xffffffffu, dot, off);
        float Mn = fmaxf(M, dot);
        float scale = expf(M - Mn);       // first iter: expf(-1e30 - Mn) == 0
        float e = expf(dot - Mn);
        S = S * scale + e;
        #pragma unroll
        for (int j = 0; j < 8; ++j) {
            acc[j].x = acc[j].x * scale + e * d[j].x;
            acc[j].y = acc[j].y * scale + e * d[j].y;
            acc[j].z = acc[j].z * scale + e * d[j].z;
            acc[j].w = acc[j].w * scale + e * d[j].w;
        }
        M = Mn;
    }
    #pragma unroll
    for (int j = 0; j < 8; ++j)
        *reinterpret_cast<float4*>(sacc + w * 1032 + j * 128 + l * 4) = acc[j];
    if (l == 0) { sM[w] = M; sS[w] = S; }
    __syncthreads();

    // phase 3: merge 16 warp-partials (warp 0)
    if (tid < 32) {
        float m = (tid < 16) ? sM[tid] : -1e30f;
        float s = (tid < 16) ? sS[tid] : 0.0f;
        float Mb = m;
        #pragma unroll
        for (int off = 16; off > 0; off >>= 1)
            Mb = fmaxf(Mb, __shfl_xor_sync(0xffffffffu, Mb, off));
        float c = expf(m - Mb);
        float sb = s * c;
        #pragma unroll
        for (int off = 16; off > 0; off >>= 1)
            sb += __shfl_xor_sync(0xffffffffu, sb, off);
        if (tid < 16) sM[tid] = c;       // overwrite with coefficients
        if (tid == 0) { sX[0] = Mb; sX[1] = sb; }
    }
    __syncthreads();

    // phase 4: each thread sums 2 cols across the 16 warp accs
    const int col = tid << 1;
    float v0 = 0.f, v1 = 0.f;
    #pragma unroll
    for (int q = 0; q < 16; ++q) {
        float c = sM[q];
        float2 a2 = *reinterpret_cast<const float2*>(sacc + q * 1032 + col);
        v0 = fmaf(a2.x, c, v0);
        v1 = fmaf(a2.y, c, v1);
    }
    *reinterpret_cast<float2*>(&g_attv[z][b * HH + col]) = make_float2(v0, v1);
    if (tid == 0) { g_attm[z][b] = sX[0]; g_atts[z][b] = sX[1]; }
}

// ---------------- attention combine: merge 4 partial softmaxes (champion) -----------
__global__ __launch_bounds__(512)
void attnc()
{
    const int b = blockIdx.x;
    const int tid = threadIdx.x;
    float m0 = g_attm[0][b], m1 = g_attm[1][b], m2 = g_attm[2][b], m3 = g_attm[3][b];
    float M = fmaxf(fmaxf(m0, m1), fmaxf(m2, m3));
    float c0 = expf(m0 - M), c1 = expf(m1 - M), c2 = expf(m2 - M), c3 = expf(m3 - M);
    float inv = 1.0f / (g_atts[0][b] * c0 + g_atts[1][b] * c1 +
                        g_atts[2][b] * c2 + g_atts[3][b] * c3);
    const int col = tid << 1;
    float2 v0 = *reinterpret_cast<const float2*>(&g_attv[0][b * HH + col]);
    float2 v1 = *reinterpret_cast<const float2*>(&g_attv[1][b * HH + col]);
    float2 v2 = *reinterpret_cast<const float2*>(&g_attv[2][b * HH + col]);
    float2 v3 = *reinterpret_cast<const float2*>(&g_attv[3][b * HH + col]);
    float2 r;
    r.x = (v0.x * c0 + v1.x * c1 + v2.x * c2 + v3.x * c3) * inv;
    r.y = (v0.y * c0 + v1.y * c1 + v2.y * c2 + v3.y * c3) * inv;
    *reinterpret_cast<float2*>(&g_value[b * HH + col]) = r;
}

// ---------------- HATT combine ------------------------------------------------------
__global__ void combine_hatt(float* __restrict__ out, const float* __restrict__ batt) {
    int idx = blockIdx.x * blockDim.x + threadIdx.x;
    int m = idx >> 10, n = idx & 1023;
    float v = g_hattp[0][idx] + g_hattp[1][idx] + g_hattp[2][idx] + g_hattp[3][idx]
            + g_hattp[4][idx] + g_hattp[5][idx] + g_hattp[6][idx] + g_hattp[7][idx]
            + batt[n];
    v = tanhf(v);
    out[(size_t)m * TD * HH + n] = v;
    g_ifeed[idx] = v;
}

// ---------------- launcher ----------------------------------------------------------
extern "C" void kernel_launch(void* const* d_in, const int* in_sizes, int n_in,
                              void* d_out, int out_size)
{
    const float* x      = (const float*)d_in[0];
    const float* o_enc  = (const float*)d_in[1];
    const float* h_enc  = (const float*)d_in[2];
    const float* Wfeed  = (const float*)d_in[3];
    const float* bfeed  = (const float*)d_in[4];
    const float* Wx     = (const float*)d_in[5];
    const float* Wh     = (const float*)d_in[6];
    const float* bxi    = (const float*)d_in[7];
    const float* bhr    = (const float*)d_in[8];
    const float* Watt   = (const float*)d_in[9];
    const float* batt   = (const float*)d_in[10];
    float* out = (float*)d_out;

    cudaFuncSetAttribute(attnp, cudaFuncAttributeMaxDynamicSharedMemorySize, ATTN_SMEM);

    init64<<<64, 1024>>>(h_enc);

    // precompute g_gxx[t] = x_t @ Wx[1024:] + bxi (recurrence-independent)
    gk2<0><<<dim3(96, TD), 256>>>(x, Wx + (size_t)HH * N3, nullptr, bxi, 0);

    for (int t = 0; t < TD; ++t) {
        gk2<1><<<dim3(32, 4), 256>>>(nullptr, Wfeed, nullptr, nullptr, 0);
        feedcomb<<<128, 512>>>(bfeed);
        gk2<2><<<dim3(96, 2, 4), 256>>>(nullptr, Wx, Wh, nullptr, t & 1);
        attnp<<<dim3(BB, 4), 512, ATTN_SMEM>>>(o_enc, bhr, t);
        attnc<<<BB, 512>>>();
        gk2<3><<<dim3(32, 2, 4), 256>>>(nullptr, Watt, nullptr, nullptr, (t + 1) & 1);
        combine_hatt<<<128, 512>>>(out + (size_t)t * HH, batt);
    }
}